// round 17
// baseline (speedup 1.0000x reference)
#include <cuda_runtime.h>
#include <cuda_fp16.h>
#include <math.h>
#include <stdint.h>

#define NN   65536
#define GG   1024
#define NPG  64
#define VV   32
#define HH   128
#define EE   1048576
#define NOUT 10

// ---------------- scratch ----------------
__device__ __half d_h2 [NN*HH];
__device__ int    d_cntm[GG*NPG*NPG];
__device__ __half d_vn [GG*VV*HH];
__device__ float  d_wc [HH*HH];
__device__ float  d_bc [HH];
__device__ __half d_wt0[6*HH*HH];   // weights (transposed [n][k], fp16)

// ================= helpers =================
__device__ __forceinline__ uint32_t smem_u32(const void* p) {
    uint32_t a;
    asm("{ .reg .u64 t; cvta.to.shared.u64 t, %1; cvt.u32.u64 %0, t; }" : "=r"(a) : "l"(p));
    return a;
}
__device__ __forceinline__ uint32_t pack_h2(__half lo, __half hi) {
    return (uint32_t)__half_as_ushort(lo) | ((uint32_t)__half_as_ushort(hi) << 16);
}
// compact blocked K-major tile, AR = atom-rows (rows/8); atom = 8r x 64 h (1KB), SW128
__device__ __forceinline__ uint32_t toff(int r, int k, int AR) {
    uint32_t base = ((((uint32_t)k >> 6) * (uint32_t)AR + ((uint32_t)r >> 3)) << 10)
                  + (((uint32_t)r & 7) << 7) + (((uint32_t)k & 63) << 1);
    return base ^ ((base >> 3) & 0x70);
}
__device__ __forceinline__ uint32_t faddr(uint32_t base, int r, int k, int AR) {
    return base + ((((uint32_t)k >> 6) * (uint32_t)AR + ((uint32_t)r >> 3)) << 10)
         + (((uint32_t)r & 7) << 7) + ((((uint32_t)k & 63) << 1) ^ (((uint32_t)r & 7) << 4));
}
__device__ __forceinline__ void ldsm4(uint32_t* r, uint32_t addr) {
    asm volatile("ldmatrix.sync.aligned.m8n8.x4.shared.b16 {%0,%1,%2,%3}, [%4];"
        : "=r"(r[0]), "=r"(r[1]), "=r"(r[2]), "=r"(r[3]) : "r"(addr));
}
__device__ __forceinline__ void mma16816(float* c, const uint32_t* a, const uint32_t* b) {
    asm volatile("mma.sync.aligned.m16n8k16.row.col.f32.f16.f16.f32 "
        "{%0,%1,%2,%3}, {%4,%5,%6,%7}, {%8,%9}, {%0,%1,%2,%3};"
        : "+f"(c[0]), "+f"(c[1]), "+f"(c[2]), "+f"(c[3])
        : "r"(a[0]), "r"(a[1]), "r"(a[2]), "r"(a[3]), "r"(b[0]), "r"(b[1]));
}

// smem layout: A tile 16KB (64x128 fp16), B tile 32KB (128x128 fp16)
#define S_A0 0
#define S_B0 16384
#define MLP_SMEM 49152
#define XG_SINV 49152
#define XG_SMEM 49408
#define NT2 256

// fused aff-mlp + att layout
#define FA_HT  49152    // hgT (AR=16, K=64) 16KB
#define FA_SEW 65536    // ew fp32, stride 33
#define FA_SMEM (65536 + 64*33*4)

// stage fp32 64x128 A tile -> fp16 (AR=8)
__device__ __forceinline__ void stage_A64f(char* smem, const float* __restrict__ A,
                                           int row0, int tid) {
    const float4* A4 = (const float4*)(A + (size_t)row0 * 128);
#pragma unroll
    for (int i = tid; i < 2048; i += NT2) {
        int r = i >> 5, k = (i & 31) << 2;
        float4 a = A4[i];
        *(uint2*)(smem + S_A0 + toff(r, k, 8)) = make_uint2(
            pack_h2(__float2half_rn(a.x), __float2half_rn(a.y)),
            pack_h2(__float2half_rn(a.z), __float2half_rn(a.w)));
    }
}
// stage fp16 64x128 A tile -> direct copy (AR=8)
__device__ __forceinline__ void stage_A64h(char* smem, const __half* __restrict__ A,
                                           int row0, int tid) {
    const uint2* A2 = (const uint2*)(A + (size_t)row0 * 128);
#pragma unroll
    for (int i = tid; i < 2048; i += NT2) {
        int r = i >> 5, k = (i & 31) << 2;
        *(uint2*)(smem + S_A0 + toff(r, k, 8)) = A2[i];
    }
}
// stage 128x128 fp16 weights into B0 (AR=16)
__device__ __forceinline__ void stage_W(char* smem, const __half* __restrict__ Wh, int tid) {
    const uint2* H = (const uint2*)Wh;
#pragma unroll
    for (int i = tid; i < 4096; i += NT2) {
        int n = i >> 5, k = (i & 31) << 2;
        *(uint2*)(smem + S_B0 + toff(n, k, 16)) = H[i];
    }
}
// one accumulating MMA pass; 8 warps: grid 2(M,32) x 4(N,32)
template<int KMAX, int ARA, int ARB>
__device__ __forceinline__ void mma_pass(uint32_t ab, uint32_t bb, int wid, int lid,
                                         float acc[2][4][4]) {
    const int m0w = (wid >> 2) * 32;
    const int n0w = (wid & 3) * 32;
    const int arow = m0w + (lid & 7) + ((lid >> 3) & 1) * 8;
    const int akad = (lid >> 4) * 8;
    const int brow0 = n0w + (lid & 7) + (lid >> 4) * 8;
    const int bkad = ((lid >> 3) & 1) * 8;
#pragma unroll
    for (int k0 = 0; k0 < KMAX; k0 += 16) {
        uint32_t a[2][4], b[2][4];
        ldsm4(a[0], faddr(ab, arow,      k0 + akad, ARA));
        ldsm4(a[1], faddr(ab, arow + 16, k0 + akad, ARA));
        ldsm4(b[0], faddr(bb, brow0,      k0 + bkad, ARB));
        ldsm4(b[1], faddr(bb, brow0 + 16, k0 + bkad, ARB));
#pragma unroll
        for (int mf = 0; mf < 2; mf++)
#pragma unroll
            for (int nf = 0; nf < 4; nf++)
                mma16816(acc[mf][nf], a[mf], &b[nf >> 1][(nf & 1) * 2]);
    }
}
__device__ __forceinline__ void zero_acc(float acc[2][4][4]) {
#pragma unroll
    for (int mf = 0; mf < 2; mf++)
#pragma unroll
        for (int nf = 0; nf < 4; nf++)
#pragma unroll
            for (int j = 0; j < 4; j++) acc[mf][nf][j] = 0.f;
}

// ---------------- weight combine ----------------
__global__ void __launch_bounds__(256) k_combine(const float* __restrict__ We,
                                                 const float* __restrict__ Wg,
                                                 const float* __restrict__ be,
                                                 float* __restrict__ Wc,
                                                 float* __restrict__ bc) {
    const int col = threadIdx.x & 127;
    const int rr  = threadIdx.x >> 7;
    for (int p = 0; p < 4; p++) {
        int row = blockIdx.x * 8 + p * 2 + rr;
        float s = 0.f;
#pragma unroll 8
        for (int k = 0; k < 128; k++) s += We[row * 128 + k] * Wg[k * 128 + col];
        Wc[row * 128 + col] = s;
    }
    if (blockIdx.x == 0 && threadIdx.x < 128) {
        float s = 0.f;
        for (int k = 0; k < 128; k++) s += be[k] * Wg[k * 128 + col];
        bc[col] = s;
    }
}

// ---------------- weight prep: transpose + fp16 round ----------------
__global__ void __launch_bounds__(128) k_split(
    const float* W0, const float* W1, const float* W2, const float* W3,
    const float* W4, const float* W5,
    __half* wt0)
{
    extern __shared__ float s[];
    const float* Ws[6] = {W0, W1, W2, W3, W4, W5};
    const float* W = Ws[blockIdx.x];
    for (int i = threadIdx.x; i < 16384; i += 128) s[i] = W[i];
    __syncthreads();
    const int n = threadIdx.x;
    uint32_t* o0 = (uint32_t*)(wt0 + (size_t)blockIdx.x * 16384 + n * 128);
    for (int k = 0; k < 128; k += 2) {
        float v0 = s[k * 128 + n], v1 = s[(k + 1) * 128 + n];
        o0[k >> 1] = pack_h2(__float2half_rn(v0), __float2half_rn(v1));
    }
}

// ------------- fused x-GEMM + GCN (1 graph per block, 64 rows) -------------
__global__ void __launch_bounds__(NT2, 3) k_xgcn(
    const float* __restrict__ x,
    const __half* __restrict__ Wch,
    const float* __restrict__ bc, const float* __restrict__ b_gcn,
    const int* __restrict__ cntm,
    __half* __restrict__ h2)
{
    extern __shared__ char smem[];
    const uint32_t sb = smem_u32(smem);
    const int tid = threadIdx.x, wid = tid >> 5, lid = tid & 31;
    const int g = blockIdx.x;
    const int row0 = g * 64;
    const int* cg = cntm + ((size_t)g << 12);
    float* sinv = (float*)(smem + XG_SINV);

    stage_A64f(smem, x, row0, tid);
    stage_W(smem, Wch, tid);
    if (tid < 64) {
        int deg = 0;
#pragma unroll 8
        for (int s = 0; s < 64; s++) deg += cg[(s << 6) + tid];
        sinv[tid] = rsqrtf((float)deg + 1.f);
    }
    __syncthreads();

    float acc[2][4][4];
    zero_acc(acc);
    mma_pass<128, 8, 16>(sb + S_A0, sb + S_B0, wid, lid, acc);

    const int m0w = (wid >> 2) * 32;
    const int n0w = (wid & 3) * 32;
    const int crow = lid >> 2;
    const int ccol = (lid & 3) * 2;

    __syncthreads();

#pragma unroll
    for (int mf = 0; mf < 2; mf++) {
        int r = m0w + mf * 16 + crow;
        float iv0 = sinv[r], iv1 = sinv[r + 8];
#pragma unroll
        for (int nf = 0; nf < 4; nf++) {
            int cn = n0w + nf * 8 + ccol;
            float2 bv = *(const float2*)(bc + cn);
            *(__half*)(smem + S_B0 + toff(cn,     r,     16)) =
                __float2half_rn((acc[mf][nf][0] + bv.x) * iv0);
            *(__half*)(smem + S_B0 + toff(cn + 1, r,     16)) =
                __float2half_rn((acc[mf][nf][1] + bv.y) * iv0);
            *(__half*)(smem + S_B0 + toff(cn,     r + 8, 16)) =
                __float2half_rn((acc[mf][nf][2] + bv.x) * iv1);
            *(__half*)(smem + S_B0 + toff(cn + 1, r + 8, 16)) =
                __float2half_rn((acc[mf][nf][3] + bv.y) * iv1);
        }
    }
    for (int i = tid; i < 4096; i += NT2) {
        int s = i >> 6, d = i & 63;
        float v = (float)cg[i] + (s == d ? 1.f : 0.f);
        *(__half*)(smem + S_A0 + toff(d, s, 8)) = __float2half_rn(v);
    }
    __syncthreads();

    zero_acc(acc);
    mma_pass<64, 8, 16>(sb + S_A0, sb + S_B0, wid, lid, acc);

#pragma unroll
    for (int mf = 0; mf < 2; mf++) {
        int r = m0w + mf * 16 + crow;
        float iv0 = sinv[r], iv1 = sinv[r + 8];
        __half* C0 = h2 + (size_t)(row0 + r) * 128;
#pragma unroll
        for (int nf = 0; nf < 4; nf++) {
            int cn = n0w + nf * 8 + ccol;
            float2 bg = *(const float2*)(b_gcn + cn);
            *(uint32_t*)(C0 + cn) = pack_h2(
                __float2half_rn(fmaxf(acc[mf][nf][0] * iv0 + bg.x, 0.f)),
                __float2half_rn(fmaxf(acc[mf][nf][1] * iv0 + bg.y, 0.f)));
            *(uint32_t*)(C0 + 8 * 128 + cn) = pack_h2(
                __float2half_rn(fmaxf(acc[mf][nf][2] * iv1 + bg.x, 0.f)),
                __float2half_rn(fmaxf(acc[mf][nf][3] * iv1 + bg.y, 0.f)));
        }
    }
}

// ---------------- edge count matrix ----------------
__global__ void k_edges(const int* __restrict__ ei, int* __restrict__ cntm) {
    int e = blockIdx.x * blockDim.x + threadIdx.x;
    int s = ei[e];
    int d = ei[EE + e];
    if ((unsigned)s >= NN || (unsigned)d >= NN) return;
    int g = s >> 6;
    atomicAdd(&cntm[(g << 12) | ((s & 63) << 6) | (d & 63)], 1);
}

// -------- fused affinity MLP + attention + pool (1 graph per block) --------
__global__ void __launch_bounds__(NT2, 2) k_affatt(
    const __half* __restrict__ h2,
    const __half* __restrict__ W1h, const float* __restrict__ b1,
    const __half* __restrict__ W2h, const float* __restrict__ b2,
    const float* __restrict__ vemb,
    const float* __restrict__ eweights,
    __half* __restrict__ vn_out)
{
    extern __shared__ char smem[];
    const uint32_t sb = smem_u32(smem);
    const int tid = threadIdx.x, wid = tid >> 5, lid = tid & 31;
    const int g = blockIdx.x;
    float* sew = (float*)(smem + FA_SEW);      // [n][v] stride 33

    // stage h2 ONCE: A tile (AR=8) for MLP + transposed hgT (AR=16,K=64) for pooling
    {
        const uint2* hg2 = (const uint2*)(h2 + (size_t)g * NPG * HH);
        for (int i = tid; i < 2048; i += NT2) {
            int n = i >> 5, h4 = (i & 31) << 2;
            uint2 t = hg2[i];
            *(uint2*)(smem + S_A0 + toff(n, h4, 8)) = t;
            __half2 p0 = *(__half2*)&t.x;
            __half2 p1 = *(__half2*)&t.y;
            *(__half*)(smem + FA_HT + toff(h4,     n, 16)) = __low2half(p0);
            *(__half*)(smem + FA_HT + toff(h4 + 1, n, 16)) = __high2half(p0);
            *(__half*)(smem + FA_HT + toff(h4 + 2, n, 16)) = __low2half(p1);
            *(__half*)(smem + FA_HT + toff(h4 + 3, n, 16)) = __high2half(p1);
        }
    }
    stage_W(smem, W1h, tid);
    __syncthreads();

    float acc[2][4][4];
    zero_acc(acc);
    mma_pass<128, 8, 16>(sb + S_A0, sb + S_B0, wid, lid, acc);

    const int m0w = (wid >> 2) * 32;
    const int n0w = (wid & 3) * 32;
    const int crow = lid >> 2;
    const int ccol = (lid & 3) * 2;

    __syncthreads();

#pragma unroll
    for (int mf = 0; mf < 2; mf++) {
        int r = m0w + mf * 16 + crow;
#pragma unroll
        for (int nf = 0; nf < 4; nf++) {
            int cn = n0w + nf * 8 + ccol;
            float2 bv = *(const float2*)(b1 + cn);
            *(uint32_t*)(smem + S_A0 + toff(r,     cn, 8)) = pack_h2(
                __float2half_rn(fmaxf(acc[mf][nf][0] + bv.x, 0.f)),
                __float2half_rn(fmaxf(acc[mf][nf][1] + bv.y, 0.f)));
            *(uint32_t*)(smem + S_A0 + toff(r + 8, cn, 8)) = pack_h2(
                __float2half_rn(fmaxf(acc[mf][nf][2] + bv.x, 0.f)),
                __float2half_rn(fmaxf(acc[mf][nf][3] + bv.y, 0.f)));
        }
    }
    stage_W(smem, W2h, tid);
    __syncthreads();

    zero_acc(acc);
    mma_pass<128, 8, 16>(sb + S_A0, sb + S_B0, wid, lid, acc);
    __syncthreads();

    // aff (+b2) -> A0 fp16 tile; vemb -> B0 rows 0-31 (fp16)
#pragma unroll
    for (int mf = 0; mf < 2; mf++) {
        int r = m0w + mf * 16 + crow;
#pragma unroll
        for (int nf = 0; nf < 4; nf++) {
            int cn = n0w + nf * 8 + ccol;
            float2 bv = *(const float2*)(b2 + cn);
            *(uint32_t*)(smem + S_A0 + toff(r,     cn, 8)) = pack_h2(
                __float2half_rn(acc[mf][nf][0] + bv.x),
                __float2half_rn(acc[mf][nf][1] + bv.y));
            *(uint32_t*)(smem + S_A0 + toff(r + 8, cn, 8)) = pack_h2(
                __float2half_rn(acc[mf][nf][2] + bv.x),
                __float2half_rn(acc[mf][nf][3] + bv.y));
        }
    }
    {
        const float4* vg4 = (const float4*)(vemb + (size_t)g * VV * HH);
        for (int i = tid; i < 1024; i += NT2) {
            int v = i >> 5, k = (i & 31) << 2;
            float4 a = vg4[i];
            *(uint2*)(smem + S_B0 + toff(v, k, 16)) = make_uint2(
                pack_h2(__float2half_rn(a.x), __float2half_rn(a.y)),
                pack_h2(__float2half_rn(a.z), __float2half_rn(a.w)));
        }
    }
    __syncthreads();

    zero_acc(acc);
    mma_pass<128, 8, 16>(sb + S_A0, sb + S_B0, wid, lid, acc);

    if (n0w == 0) {
        const float* ew_g = eweights + (size_t)g * NPG * VV;
        const float scale = 0.08838834764831845f;
#pragma unroll
        for (int mf = 0; mf < 2; mf++) {
            int n = m0w + mf * 16 + crow;
#pragma unroll
            for (int nf = 0; nf < 4; nf++) {
                int v = nf * 8 + ccol;
#pragma unroll
                for (int j = 0; j < 4; j++) {
                    int nn = n + (j >> 1) * 8;
                    int vv = v + (j & 1);
                    float att = acc[mf][nf][j] * scale;
                    float sg = 1.f / (1.f + expf(-att));
                    sew[nn * 33 + vv] = ew_g[nn * 32 + vv] * (1.f + sg);
                }
            }
        }
    }
    __syncthreads();

    if (tid < NPG) {
        float rs = 0.f;
#pragma unroll 8
        for (int v = 0; v < VV; v++) rs += sew[tid * 33 + v];
        float ivr = 1.f / ((rs == 0.f) ? 1.f : rs);
#pragma unroll 8
        for (int v = 0; v < VV; v++) sew[tid * 33 + v] *= ivr;
    }
    __syncthreads();

    for (int i = tid; i < 2048; i += NT2) {
        int v = i >> 6, n = i & 63;
        *(__half*)(smem + S_A0 + toff(v, n, 4)) = __float2half_rn(sew[n * 33 + v]);
    }
    __syncthreads();

    zero_acc(acc);
    mma_pass<64, 4, 16>(sb + S_A0, sb + FA_HT, wid, lid, acc);

    if (m0w == 0) {
#pragma unroll
        for (int mf = 0; mf < 2; mf++) {
            int v = mf * 16 + crow;
            __half* C0 = vn_out + (size_t)(g * VV + v) * 128;
            __half* C8 = vn_out + (size_t)(g * VV + v + 8) * 128;
#pragma unroll
            for (int nf = 0; nf < 4; nf++) {
                int cn = n0w + nf * 8 + ccol;
                *(uint32_t*)(C0 + cn) = pack_h2(
                    __float2half_rn(acc[mf][nf][0]), __float2half_rn(acc[mf][nf][1]));
                *(uint32_t*)(C8 + cn) = pack_h2(
                    __float2half_rn(acc[mf][nf][2]), __float2half_rn(acc[mf][nf][3]));
            }
        }
    }
}

// -------- fused tail: vn-MLP2 + mean over V + final MLP + head (2 graphs/block) -------
#define VT_GF  49152                         // gf 2x128 fp32 (1 KB)
#define VT_T1  50176                         // t1 2x128 fp32 (1 KB)
#define VT_SMEM 51200
__global__ void __launch_bounds__(NT2, 3) k_vntail(
    const __half* __restrict__ vn,
    const __half* __restrict__ W1h, const float* __restrict__ b1,
    const __half* __restrict__ W2h, const float* __restrict__ b2,
    const float* __restrict__ mW1, const float* __restrict__ mb1,
    const float* __restrict__ mW2, const float* __restrict__ mb2,
    float* __restrict__ out)
{
    extern __shared__ char smem[];
    const uint32_t sb = smem_u32(smem);
    const int tid = threadIdx.x, wid = tid >> 5, lid = tid & 31;
    const int row0 = blockIdx.x * 64;        // 2 graphs: g0, g0+1
    const int g0 = row0 >> 5;

    stage_A64h(smem, vn, row0, tid);
    stage_W(smem, W1h, tid);
    __syncthreads();

    float acc[2][4][4];
    zero_acc(acc);
    mma_pass<128, 8, 16>(sb + S_A0, sb + S_B0, wid, lid, acc);

    const int m0w = (wid >> 2) * 32;
    const int n0w = (wid & 3) * 32;
    const int crow = lid >> 2;
    const int ccol = (lid & 3) * 2;

    __syncthreads();

    // relu(t + b1) restage fp16 into A0
#pragma unroll
    for (int mf = 0; mf < 2; mf++) {
        int r = m0w + mf * 16 + crow;
#pragma unroll
        for (int nf = 0; nf < 4; nf++) {
            int cn = n0w + nf * 8 + ccol;
            float2 bv = *(const float2*)(b1 + cn);
            *(uint32_t*)(smem + S_A0 + toff(r,     cn, 8)) = pack_h2(
                __float2half_rn(fmaxf(acc[mf][nf][0] + bv.x, 0.f)),
                __float2half_rn(fmaxf(acc[mf][nf][1] + bv.y, 0.f)));
            *(uint32_t*)(smem + S_A0 + toff(r + 8, cn, 8)) = pack_h2(
                __float2half_rn(fmaxf(acc[mf][nf][2] + bv.x, 0.f)),
                __float2half_rn(fmaxf(acc[mf][nf][3] + bv.y, 0.f)));
        }
    }
    stage_W(smem, W2h, tid);
    __syncthreads();

    zero_acc(acc);
    mma_pass<128, 8, 16>(sb + S_A0, sb + S_B0, wid, lid, acc);
    __syncthreads();   // B0 reads done; repurpose as fp32 vn2

    // vn2 (+b2) -> fp32 smem [64][128] over B0
    float* v2s = (float*)(smem + S_B0);
#pragma unroll
    for (int mf = 0; mf < 2; mf++) {
        int r = m0w + mf * 16 + crow;
#pragma unroll
        for (int nf = 0; nf < 4; nf++) {
            int cn = n0w + nf * 8 + ccol;
            float2 bv = *(const float2*)(b2 + cn);
            v2s[r * 128 + cn]           = acc[mf][nf][0] + bv.x;
            v2s[r * 128 + cn + 1]       = acc[mf][nf][1] + bv.y;
            v2s[(r + 8) * 128 + cn]     = acc[mf][nf][2] + bv.x;
            v2s[(r + 8) * 128 + cn + 1] = acc[mf][nf][3] + bv.y;
        }
    }
    __syncthreads();

    // gf[gl][h] = mean over 32 V rows
    float* gf = (float*)(smem + VT_GF);
    {
        int gl = tid >> 7, h = tid & 127;
        const float* base = v2s + gl * 32 * 128 + h;
        float s = 0.f;
#pragma unroll 8
        for (int v = 0; v < VV; v++) s += base[v * 128];
        gf[gl * 128 + h] = s * (1.f / 32.f);
    }
    __syncthreads();

    // t1[gl][n] = relu(gf[gl] @ mW1[:,n] + mb1[n])
    float* t1 = (float*)(smem + VT_T1);
    {
        int gl = tid >> 7, n = tid & 127;
        const float* gr = gf + gl * 128;
        float s = mb1[n];
#pragma unroll 8
        for (int k = 0; k < 128; k++) s += gr[k] * mW1[k * 128 + n];
        t1[gl * 128 + n] = fmaxf(s, 0.f);
    }
    __syncthreads();

    // out[g0+gl][o] = t1[gl] @ mW2[:,o] + mb2[o]
    if (tid < 2 * NOUT) {
        int gl = tid / NOUT, o = tid - gl * NOUT;
        const float* tr = t1 + gl * 128;
        float s = mb2[o];
#pragma unroll 8
        for (int k = 0; k < 128; k++) s += tr[k] * mW2[k * NOUT + o];
        out[(size_t)(g0 + gl) * NOUT + o] = s;
    }
}

// ---------------- launcher ----------------
extern "C" void kernel_launch(void* const* d_in, const int* in_sizes, int n_in,
                              void* d_out, int out_size)
{
    (void)in_sizes; (void)n_in; (void)out_size;
    const float* x        = (const float*)d_in[0];
    const int*   ei       = (const int*)d_in[1];
    const float* eweights = (const float*)d_in[3];
    const float* vemb     = (const float*)d_in[4];
    const float* W_emb  = (const float*)d_in[5];  const float* b_emb  = (const float*)d_in[6];
    const float* W_gcn  = (const float*)d_in[7];  const float* b_gcn  = (const float*)d_in[8];
    const float* aff_W1 = (const float*)d_in[9];  const float* aff_b1 = (const float*)d_in[10];
    const float* aff_W2 = (const float*)d_in[11]; const float* aff_b2 = (const float*)d_in[12];
    const float* vn_W1  = (const float*)d_in[13]; const float* vn_b1  = (const float*)d_in[14];
    const float* vn_W2  = (const float*)d_in[15]; const float* vn_b2  = (const float*)d_in[16];
    const float* mlp_W1 = (const float*)d_in[17]; const float* mlp_b1 = (const float*)d_in[18];
    const float* mlp_W2 = (const float*)d_in[19]; const float* mlp_b2 = (const float*)d_in[20];
    float* out = (float*)d_out;

    __half *p_h2, *p_vn, *p_wt0;
    float *p_wc, *p_bc;
    int *p_cntm;
    cudaGetSymbolAddress((void**)&p_h2,   d_h2);
    cudaGetSymbolAddress((void**)&p_cntm, d_cntm);
    cudaGetSymbolAddress((void**)&p_vn,   d_vn);
    cudaGetSymbolAddress((void**)&p_wc,   d_wc);
    cudaGetSymbolAddress((void**)&p_bc,   d_bc);
    cudaGetSymbolAddress((void**)&p_wt0,  d_wt0);

    cudaFuncSetAttribute(k_split,  cudaFuncAttributeMaxDynamicSharedMemorySize, 65536);
    cudaFuncSetAttribute(k_xgcn,   cudaFuncAttributeMaxDynamicSharedMemorySize, XG_SMEM);
    cudaFuncSetAttribute(k_affatt, cudaFuncAttributeMaxDynamicSharedMemorySize, FA_SMEM);
    cudaFuncSetAttribute(k_vntail, cudaFuncAttributeMaxDynamicSharedMemorySize, VT_SMEM);

    #define WT0(i) (p_wt0 + (size_t)(i) * 16384)

    // 0) combined weight + fp16 weight prep (slots: 0=Wc, 1=aff1, 2=aff2, 3=vn1, 4=vn2, 5=mlp1)
    k_combine<<<16, 256>>>(W_emb, W_gcn, b_emb, p_wc, p_bc);
    k_split<<<6, 128, 65536>>>(p_wc, aff_W1, aff_W2, vn_W1, vn_W2, mlp_W1, p_wt0);

    // 1) edge count matrix
    cudaMemsetAsync(p_cntm, 0, (size_t)GG * NPG * NPG * sizeof(int));
    k_edges<<<EE/256, 256>>>(ei, p_cntm);

    // 2) fused x-GEMM + GCN -> h2 (fp16)
    k_xgcn<<<GG, NT2, XG_SMEM>>>(x, WT0(0), p_bc, b_gcn, p_cntm, p_h2);

    // 3) fused affinity MLP + attention + pool -> vn
    k_affatt<<<GG, NT2, FA_SMEM>>>(p_h2, WT0(1), aff_b1, WT0(2), aff_b2,
                                   vemb, eweights, p_vn);

    // 4) fused vn-MLP + mean + final MLP + head -> out
    k_vntail<<<GG*VV/64, NT2, VT_SMEM>>>(p_vn, WT0(3), vn_b1, WT0(4), vn_b2,
                                         mlp_W1, mlp_b1, mlp_W2, mlp_b2, out);
}